// round 3
// baseline (speedup 1.0000x reference)
#include <cuda_runtime.h>
#include <math.h>

// ============================================================================
// Problem constants
// ============================================================================
#define B_     2
#define S_     2048
#define IN_DIM 1024
#define P_DIM  512
#define H_     8
#define HD_    64
#define NPENTA 1024
#define KNEI   128
#define ROWS   (B_ * S_)        // 4096
#define EPS_   1e-5f

// ============================================================================
// Scratch (static device globals — no runtime allocation)
// ============================================================================
__device__ float g_cent[NPENTA * P_DIM];          //  2 MB  normalized centroids
__device__ float g_zpre[ROWS * P_DIM];            //  8 MB  proj output (pre-LN)
__device__ float g_z[ROWS * P_DIM];               //  8 MB  normalized activations
__device__ float g_scores[ROWS * NPENTA];         // 16 MB  z . cent^T
__device__ float g_pos[ROWS];                     //        cantor positions
__device__ int   g_routes[ROWS * KNEI];           //  2 MB  neighbor indices
__device__ float g_qkv[ROWS * 3 * P_DIM];         // 24 MB
__device__ float g_att[ROWS * P_DIM];             //  8 MB  attention output
__device__ float g_attpart[B_ * 16 * P_DIM];      //        partial sums for mean
__device__ float g_attmean[B_ * P_DIM];
__device__ float g_pooled[B_ * P_DIM];
__device__ float g_h[B_ * 1024];                  //        MLP hidden scratch

// ============================================================================
// Helpers
// ============================================================================
__device__ __forceinline__ float gelu_exact(float x) {
    return 0.5f * x * (1.0f + erff(x * 0.70710678118654752440f));
}

// Block tree reduction (n = blockDim.x, power of two). Returns result to all.
__device__ __forceinline__ float block_sum(float v, float* red, int n, int tid) {
    red[tid] = v;
    __syncthreads();
    for (int s = n >> 1; s > 0; s >>= 1) {
        if (tid < s) red[tid] += red[tid + s];
        __syncthreads();
    }
    float r = red[0];
    __syncthreads();
    return r;
}

// ============================================================================
// Kernel 1: centroids = normalize(mean over 5 vertices)
// ============================================================================
__global__ void k_cent(const float* __restrict__ penta) {
    __shared__ float red[256];
    int p = blockIdx.x, tid = threadIdx.x;   // 256 threads, 2 dims each
    float v[2];
    float ss = 0.f;
#pragma unroll
    for (int r = 0; r < 2; r++) {
        int d = tid + r * 256;
        float s = 0.f;
#pragma unroll
        for (int i = 0; i < 5; i++) s += penta[(p * 5 + i) * P_DIM + d];
        v[r] = s / 5.0f;
        ss += v[r] * v[r];
    }
    float tot = block_sum(ss, red, 256, tid);
    float den = fmaxf(sqrtf(tot), 1e-12f);
#pragma unroll
    for (int r = 0; r < 2; r++) g_cent[p * P_DIM + tid + r * 256] = v[r] / den;
}

// ============================================================================
// Tiled SGEMM: C[M,N] = A[M,K] @ B + bias.  TB: B is [N,K] (compute A.B^T).
// block 256 threads, 128x128 tile, BK=8, 8x8 per thread. M,N multiples of 128,
// K multiple of 8.
// ============================================================================
template <int M, int N, int K, bool TB, bool BIAS>
__device__ __forceinline__ void sgemm_body(const float* __restrict__ A,
                                           const float* __restrict__ Bm,
                                           const float* __restrict__ bias,
                                           float* __restrict__ C) {
    __shared__ float As[8][128];
    __shared__ float Bs[8][128];
    const int tid  = threadIdx.x;
    const int row0 = blockIdx.y * 128, col0 = blockIdx.x * 128;
    const int tr = (tid >> 4) << 3;
    const int tc = (tid & 15) << 3;
    const int a_r = tid >> 1, a_c = (tid & 1) << 2;
    const int b_r = tid >> 5, b_c = (tid & 31) << 2;

    float acc[8][8];
#pragma unroll
    for (int i = 0; i < 8; i++)
#pragma unroll
        for (int j = 0; j < 8; j++) acc[i][j] = 0.f;

    for (int k0 = 0; k0 < K; k0 += 8) {
        float4 av = *(const float4*)(A + (size_t)(row0 + a_r) * K + k0 + a_c);
        As[a_c + 0][a_r] = av.x; As[a_c + 1][a_r] = av.y;
        As[a_c + 2][a_r] = av.z; As[a_c + 3][a_r] = av.w;
        if (!TB) {
            *(float4*)(&Bs[b_r][b_c]) =
                *(const float4*)(Bm + (size_t)(k0 + b_r) * N + col0 + b_c);
        } else {
            float4 bv = *(const float4*)(Bm + (size_t)(col0 + a_r) * K + k0 + a_c);
            Bs[a_c + 0][a_r] = bv.x; Bs[a_c + 1][a_r] = bv.y;
            Bs[a_c + 2][a_r] = bv.z; Bs[a_c + 3][a_r] = bv.w;
        }
        __syncthreads();
#pragma unroll
        for (int kk = 0; kk < 8; kk++) {
            float ar[8], br[8];
            *(float4*)(ar)     = *(const float4*)&As[kk][tr];
            *(float4*)(ar + 4) = *(const float4*)&As[kk][tr + 4];
            *(float4*)(br)     = *(const float4*)&Bs[kk][tc];
            *(float4*)(br + 4) = *(const float4*)&Bs[kk][tc + 4];
#pragma unroll
            for (int i = 0; i < 8; i++)
#pragma unroll
                for (int j = 0; j < 8; j++) acc[i][j] += ar[i] * br[j];
        }
        __syncthreads();
    }
#pragma unroll
    for (int i = 0; i < 8; i++) {
#pragma unroll
        for (int j = 0; j < 8; j++) {
            float v = acc[i][j];
            if (BIAS) v += bias[col0 + tc + j];
            C[(size_t)(row0 + tr + i) * N + col0 + tc + j] = v;
        }
    }
}

__global__ void __launch_bounds__(256)
k_gemm_proj(const float* __restrict__ X, const float* __restrict__ W,
            const float* __restrict__ b) {
    sgemm_body<ROWS, P_DIM, IN_DIM, false, true>(X, W, b, g_zpre);
}
__global__ void __launch_bounds__(256) k_gemm_scores() {
    sgemm_body<ROWS, NPENTA, P_DIM, true, false>(g_z, g_cent, nullptr, g_scores);
}
__global__ void __launch_bounds__(256)
k_gemm_qkv(const float* __restrict__ W, const float* __restrict__ b) {
    sgemm_body<ROWS, 3 * P_DIM, P_DIM, false, true>(g_z, W, b, g_qkv);
}

// ============================================================================
// Kernel: LayerNorm + GELU + L2-normalize per row (512). 256 threads, 2/thread.
// ============================================================================
__global__ void k_lgn(const float* __restrict__ gam, const float* __restrict__ bet) {
    __shared__ float red[256];
    int row = blockIdx.x, tid = threadIdx.x;
    const float* src = g_zpre + (size_t)row * P_DIM;
    float x0 = src[tid], x1 = src[tid + 256];
    float mu = block_sum(x0 + x1, red, 256, tid) / 512.0f;
    float d0 = x0 - mu, d1 = x1 - mu;
    float var = block_sum(d0 * d0 + d1 * d1, red, 256, tid) / 512.0f;
    float rs = rsqrtf(var + EPS_);
    float y0 = d0 * rs * gam[tid] + bet[tid];
    float y1 = d1 * rs * gam[tid + 256] + bet[tid + 256];
    float h0 = gelu_exact(y0), h1 = gelu_exact(y1);
    float nrm = sqrtf(block_sum(h0 * h0 + h1 * h1, red, 256, tid));
    float den = fmaxf(nrm, 1e-12f);
    float* dst = g_z + (size_t)row * P_DIM;
    dst[tid] = h0 / den;
    dst[tid + 256] = h1 / den;
}

// ============================================================================
// Kernel: argmax over 1024 centroids (first-index tie-break) -> gather position
// ============================================================================
__global__ void k_anchor(const float* __restrict__ positions) {
    __shared__ float bv[256];
    __shared__ int   bi[256];
    int row = blockIdx.x, tid = threadIdx.x;
    float best = -1e30f;
    int   bidx = 0;
    for (int p = tid; p < NPENTA; p += 256) {   // ascending -> strict > keeps first
        float v = g_scores[(size_t)row * NPENTA + p];
        if (v > best) { best = v; bidx = p; }
    }
    bv[tid] = best; bi[tid] = bidx;
    __syncthreads();
    for (int s = 128; s > 0; s >>= 1) {
        if (tid < s) {
            if (bv[tid + s] > bv[tid] ||
                (bv[tid + s] == bv[tid] && bi[tid + s] < bi[tid])) {
                bv[tid] = bv[tid + s]; bi[tid] = bi[tid + s];
            }
        }
        __syncthreads();
    }
    if (tid == 0) g_pos[row] = positions[bi[0]];
}

// ============================================================================
// Kernel: exact 128-NN selection. key = (float_bits(dist)<<32)|index gives the
// same total order as jax top_k(-dist) (dist asc, index asc). Bitonic sort of
// 2048 keys in smem, keep first 128.
// ============================================================================
__global__ void k_topk() {
    __shared__ float spos[S_];
    __shared__ unsigned long long keys[S_];
    int row = blockIdx.x;
    int b = row >> 11;
    int tid = threadIdx.x;   // 256
    for (int i = tid; i < S_; i += 256) spos[i] = g_pos[b * S_ + i];
    __syncthreads();
    float pq = spos[row & (S_ - 1)];
    for (int i = tid; i < S_; i += 256) {
        unsigned int db = __float_as_uint(fabsf(pq - spos[i]));
        keys[i] = ((unsigned long long)db << 32) | (unsigned int)i;
    }
    __syncthreads();
    for (int len = 2; len <= S_; len <<= 1) {
        for (int j = len >> 1; j > 0; j >>= 1) {
            for (int i = tid; i < S_; i += 256) {
                int p = i ^ j;
                if (p > i) {
                    bool up = ((i & len) == 0);
                    unsigned long long a = keys[i], c = keys[p];
                    if ((a > c) == up) { keys[i] = c; keys[p] = a; }
                }
            }
            __syncthreads();
        }
    }
    if (tid < KNEI)
        g_routes[(size_t)row * KNEI + tid] = (int)(keys[tid] & 0xffffffffu);
}

// ============================================================================
// Kernel: gathered attention. Block per (b,q); heads sequential; k/v tiles
// staged in padded smem (pad 65 -> conflict-free row and column access).
// ============================================================================
__global__ void __launch_bounds__(256) k_attention() {
    __shared__ int   rbase[KNEI];
    __shared__ float qv[HD_];
    __shared__ float sc[KNEI];
    __shared__ float red2[2];
    __shared__ float tile[KNEI][HD_ + 1];
    int row = blockIdx.x;
    int b = row >> 11;
    int tid = threadIdx.x;
    if (tid < KNEI)
        rbase[tid] = (b * S_ + g_routes[(size_t)row * KNEI + tid]) * (3 * P_DIM);
    __syncthreads();

    for (int h = 0; h < H_; h++) {
        int hoff = h * HD_;
        if (tid < HD_) qv[tid] = g_qkv[(size_t)row * 3 * P_DIM + hoff + tid];
        // K tile
#pragma unroll 4
        for (int e = tid; e < KNEI * HD_; e += 256) {
            int i = e >> 6, d = e & 63;
            tile[i][d] = g_qkv[rbase[i] + P_DIM + hoff + d];
        }
        __syncthreads();
        if (tid < KNEI) {
            float s = 0.f;
#pragma unroll
            for (int d = 0; d < HD_; d++) s += qv[d] * tile[tid][d];
            sc[tid] = s * 0.125f;
        }
        __syncthreads();
        if (tid < 32) {
            float m = fmaxf(fmaxf(sc[tid], sc[tid + 32]),
                            fmaxf(sc[tid + 64], sc[tid + 96]));
#pragma unroll
            for (int o = 16; o; o >>= 1) m = fmaxf(m, __shfl_xor_sync(0xffffffffu, m, o));
            red2[0] = m;
        }
        __syncthreads();
        float mx = red2[0];
        if (tid < KNEI) sc[tid] = expf(sc[tid] - mx);
        __syncthreads();
        if (tid < 32) {
            float s = sc[tid] + sc[tid + 32] + sc[tid + 64] + sc[tid + 96];
#pragma unroll
            for (int o = 16; o; o >>= 1) s += __shfl_xor_sync(0xffffffffu, s, o);
            red2[1] = s;
        }
        __syncthreads();
        float inv = 1.0f / red2[1];
        // V tile (overwrite)
#pragma unroll 4
        for (int e = tid; e < KNEI * HD_; e += 256) {
            int i = e >> 6, d = e & 63;
            tile[i][d] = g_qkv[rbase[i] + 2 * P_DIM + hoff + d];
        }
        __syncthreads();
        if (tid < HD_) {
            float o = 0.f;
#pragma unroll
            for (int i = 0; i < KNEI; i++) o += sc[i] * tile[i][tid];
            g_att[(size_t)row * P_DIM + hoff + tid] = o * inv;
        }
        __syncthreads();
    }
}

// ============================================================================
// Pooling (deterministic two-stage) + out projection folded after the mean
// ============================================================================
__global__ void k_attmean1() {
    int bb = blockIdx.x;             // 128 blocks: b(2) * dc(4) * sc(16)
    int b  = bb >> 6;
    int dc = (bb >> 4) & 3;
    int sc = bb & 15;
    int d = dc * 128 + threadIdx.x;  // 128 threads
    float s = 0.f;
    int base = (b * S_ + sc * 128) * P_DIM + d;
    for (int t = 0; t < 128; t++) s += g_att[base + t * P_DIM];
    g_attpart[(b * 16 + sc) * P_DIM + d] = s;
}
__global__ void k_attmean2() {
    int b = blockIdx.x >> 2, dc = blockIdx.x & 3;   // 8 blocks, 128 threads
    int d = dc * 128 + threadIdx.x;
    float s = 0.f;
#pragma unroll
    for (int p = 0; p < 16; p++) s += g_attpart[(b * 16 + p) * P_DIM + d];
    g_attmean[b * P_DIM + d] = s * (1.0f / (float)S_);
}
__global__ void k_pool(const float* __restrict__ outW, const float* __restrict__ outb) {
    __shared__ float am[P_DIM];
    int b = blockIdx.x, n = threadIdx.x;   // 512 threads
    am[n] = g_attmean[b * P_DIM + n];
    __syncthreads();
    float acc = outb[n];
#pragma unroll 8
    for (int k = 0; k < P_DIM; k++) acc += am[k] * outW[k * P_DIM + n];
    g_pooled[b * P_DIM + n] = acc;
}

// ============================================================================
// Per-scale MLP heads
// ============================================================================
template <int TWOS>
__global__ void k_mlp1(const float* __restrict__ w1, const float* __restrict__ b1,
                       const float* __restrict__ gam, const float* __restrict__ bet) {
    __shared__ float pr[P_DIM];
    __shared__ float red[TWOS];
    int b = blockIdx.x, j = threadIdx.x;   // TWOS threads
    for (int k = j; k < P_DIM; k += TWOS) pr[k] = g_pooled[b * P_DIM + k];
    __syncthreads();
    float t = b1[j];
#pragma unroll 8
    for (int k = 0; k < P_DIM; k++) t += pr[k] * w1[k * TWOS + j];
    float mu = block_sum(t, red, TWOS, j) / (float)TWOS;
    float d = t - mu;
    float var = block_sum(d * d, red, TWOS, j) / (float)TWOS;
    float y = d * rsqrtf(var + EPS_) * gam[j] + bet[j];
    g_h[b * 1024 + j] = gelu_exact(y);
}

template <int TWOS, int SS, int OFF>
__global__ void k_mlp2(const float* __restrict__ w2, const float* __restrict__ b2,
                       float* __restrict__ out) {
    __shared__ float hr[TWOS];
    int b = blockIdx.x, j = threadIdx.x;   // SS threads
    for (int k = j; k < TWOS; k += SS) hr[k] = g_h[b * 1024 + k];
    __syncthreads();
    float acc = b2[j];
#pragma unroll 8
    for (int k = 0; k < TWOS; k++) acc += hr[k] * w2[k * SS + j];
    out[b * 896 + OFF + j] = acc;
}

// ============================================================================
// Launch
// ============================================================================
extern "C" void kernel_launch(void* const* d_in, const int* in_sizes, int n_in,
                              void* d_out, int out_size) {
    const float* X      = (const float*)d_in[0];
    const float* penta  = (const float*)d_in[1];
    const float* poss   = (const float*)d_in[2];
    const float* projW  = (const float*)d_in[3];
    const float* projb  = (const float*)d_in[4];
    const float* lng    = (const float*)d_in[5];
    const float* lnb    = (const float*)d_in[6];
    const float* qkvW   = (const float*)d_in[7];
    const float* qkvb   = (const float*)d_in[8];
    const float* outW   = (const float*)d_in[9];
    const float* outb   = (const float*)d_in[10];
    const float* w1a = (const float*)d_in[11]; const float* b1a = (const float*)d_in[12];
    const float* ga  = (const float*)d_in[13]; const float* bba = (const float*)d_in[14];
    const float* w2a = (const float*)d_in[15]; const float* b2a = (const float*)d_in[16];
    const float* w1b = (const float*)d_in[17]; const float* b1b = (const float*)d_in[18];
    const float* gb  = (const float*)d_in[19]; const float* bbb = (const float*)d_in[20];
    const float* w2b = (const float*)d_in[21]; const float* b2b = (const float*)d_in[22];
    const float* w1c = (const float*)d_in[23]; const float* b1c = (const float*)d_in[24];
    const float* gc  = (const float*)d_in[25]; const float* bbc = (const float*)d_in[26];
    const float* w2c = (const float*)d_in[27]; const float* b2c = (const float*)d_in[28];
    float* out = (float*)d_out;

    k_cent<<<NPENTA, 256>>>(penta);
    k_gemm_proj<<<dim3(P_DIM / 128, ROWS / 128), 256>>>(X, projW, projb);
    k_lgn<<<ROWS, 256>>>(lng, lnb);
    k_gemm_scores<<<dim3(NPENTA / 128, ROWS / 128), 256>>>();
    k_anchor<<<ROWS, 256>>>(poss);
    k_gemm_qkv<<<dim3(3 * P_DIM / 128, ROWS / 128), 256>>>(qkvW, qkvb);
    k_topk<<<ROWS, 256>>>();
    k_attention<<<ROWS, 256>>>();
    k_attmean1<<<128, 128>>>();
    k_attmean2<<<8, 128>>>();
    k_pool<<<B_, 512>>>(outW, outb);

    k_mlp1<256><<<B_, 256>>>(w1a, b1a, ga, bba);
    k_mlp2<256, 128, 0><<<B_, 128>>>(w2a, b2a, out);
    k_mlp1<512><<<B_, 512>>>(w1b, b1b, gb, bbb);
    k_mlp2<512, 256, 128><<<B_, 256>>>(w2b, b2b, out);
    k_mlp1<1024><<<B_, 1024>>>(w1c, b1c, gc, bbc);
    k_mlp2<1024, 512, 384><<<B_, 512>>>(w2c, b2c, out);
}

// round 4
// speedup vs baseline: 1.3427x; 1.3427x over previous
#include <cuda_runtime.h>
#include <math.h>

// ============================================================================
// Problem constants
// ============================================================================
#define B_     2
#define S_     2048
#define IN_DIM 1024
#define P_DIM  512
#define H_     8
#define HD_    64
#define NPENTA 1024
#define KNEI   128
#define ROWS   (B_ * S_)        // 4096
#define EPS_   1e-5f

// ============================================================================
// Scratch (static device globals — no runtime allocation)
// ============================================================================
__device__ float g_cent[NPENTA * P_DIM];          //  2 MB  normalized centroids
__device__ float g_zpre[ROWS * P_DIM];            //  8 MB  proj output (pre-LN)
__device__ float g_z[ROWS * P_DIM];               //  8 MB  normalized activations
__device__ float g_pval[ROWS * 8];                //        per-colblock argmax partials
__device__ int   g_pidx[ROWS * 8];
__device__ int   g_anchor[ROWS];                  //        anchor id per token
__device__ int   g_routes[B_ * NPENTA * KNEI];    //  1 MB  routes per (batch, anchor)
__device__ float g_qkv[ROWS * 3 * P_DIM];         // 24 MB
__device__ float g_att[ROWS * P_DIM];             //  8 MB  attention output
__device__ float g_attpart[B_ * 16 * P_DIM];
__device__ float g_attmean[B_ * P_DIM];
__device__ float g_pooled[B_ * P_DIM];
__device__ float g_h[B_ * 1024];

// ============================================================================
// Helpers
// ============================================================================
__device__ __forceinline__ float gelu_exact(float x) {
    return 0.5f * x * (1.0f + erff(x * 0.70710678118654752440f));
}

__device__ __forceinline__ float block_sum(float v, float* red, int n, int tid) {
    red[tid] = v;
    __syncthreads();
    for (int s = n >> 1; s > 0; s >>= 1) {
        if (tid < s) red[tid] += red[tid + s];
        __syncthreads();
    }
    float r = red[0];
    __syncthreads();
    return r;
}

// ============================================================================
// centroids = normalize(mean over 5 vertices)
// ============================================================================
__global__ void k_cent(const float* __restrict__ penta) {
    __shared__ float red[256];
    int p = blockIdx.x, tid = threadIdx.x;
    float v[2];
    float ss = 0.f;
#pragma unroll
    for (int r = 0; r < 2; r++) {
        int d = tid + r * 256;
        float s = 0.f;
#pragma unroll
        for (int i = 0; i < 5; i++) s += penta[(p * 5 + i) * P_DIM + d];
        v[r] = s / 5.0f;
        ss += v[r] * v[r];
    }
    float tot = block_sum(ss, red, 256, tid);
    float den = fmaxf(sqrtf(tot), 1e-12f);
#pragma unroll
    for (int r = 0; r < 2; r++) g_cent[p * P_DIM + tid + r * 256] = v[r] / den;
}

// ============================================================================
// Double-buffered tiled SGEMM: C = A[M,K] @ B (+bias). TB: B is [N,K].
// 256 threads, 128x128 tile, BK=8, 8x8 per thread. Optional fused argmax
// epilogue (first-index tie-break, exact): writes per-colblock partials
// instead of C.
// ============================================================================
template <int M, int N, int K, bool TB, bool BIAS, bool ARGMAX>
__device__ __forceinline__ void sgemm_body(const float* __restrict__ A,
                                           const float* __restrict__ Bm,
                                           const float* __restrict__ bias,
                                           float* __restrict__ C) {
    __shared__ float As[2][8][128];
    __shared__ float Bs[2][8][128];
    const int tid  = threadIdx.x;
    const int row0 = blockIdx.y * 128, col0 = blockIdx.x * 128;
    const int tr = (tid >> 4) << 3;
    const int tc = (tid & 15) << 3;
    const int a_r = tid >> 1, a_c = (tid & 1) << 2;
    const int b_r = tid >> 5, b_c = (tid & 31) << 2;

    const float* aPtr = A + (size_t)(row0 + a_r) * K + a_c;

    float acc[8][8];
#pragma unroll
    for (int i = 0; i < 8; i++)
#pragma unroll
        for (int j = 0; j < 8; j++) acc[i][j] = 0.f;

    // preload tile 0
    float4 av = *(const float4*)(aPtr);
    float4 bv;
    if (!TB) bv = *(const float4*)(Bm + (size_t)b_r * N + col0 + b_c);
    else     bv = *(const float4*)(Bm + (size_t)(col0 + a_r) * K + a_c);
    As[0][a_c + 0][a_r] = av.x; As[0][a_c + 1][a_r] = av.y;
    As[0][a_c + 2][a_r] = av.z; As[0][a_c + 3][a_r] = av.w;
    if (!TB) {
        *(float4*)(&Bs[0][b_r][b_c]) = bv;
    } else {
        Bs[0][a_c + 0][a_r] = bv.x; Bs[0][a_c + 1][a_r] = bv.y;
        Bs[0][a_c + 2][a_r] = bv.z; Bs[0][a_c + 3][a_r] = bv.w;
    }
    __syncthreads();

    int buf = 0;
    for (int k0 = 8; k0 < K + 8; k0 += 8) {
        if (k0 < K) {
            av = *(const float4*)(aPtr + k0);
            if (!TB) bv = *(const float4*)(Bm + (size_t)(k0 + b_r) * N + col0 + b_c);
            else     bv = *(const float4*)(Bm + (size_t)(col0 + a_r) * K + k0 + a_c);
        }
#pragma unroll
        for (int kk = 0; kk < 8; kk++) {
            float ar[8], br[8];
            *(float4*)(ar)     = *(const float4*)&As[buf][kk][tr];
            *(float4*)(ar + 4) = *(const float4*)&As[buf][kk][tr + 4];
            *(float4*)(br)     = *(const float4*)&Bs[buf][kk][tc];
            *(float4*)(br + 4) = *(const float4*)&Bs[buf][kk][tc + 4];
#pragma unroll
            for (int i = 0; i < 8; i++)
#pragma unroll
                for (int j = 0; j < 8; j++) acc[i][j] += ar[i] * br[j];
        }
        if (k0 < K) {
            int nb = buf ^ 1;
            As[nb][a_c + 0][a_r] = av.x; As[nb][a_c + 1][a_r] = av.y;
            As[nb][a_c + 2][a_r] = av.z; As[nb][a_c + 3][a_r] = av.w;
            if (!TB) {
                *(float4*)(&Bs[nb][b_r][b_c]) = bv;
            } else {
                Bs[nb][a_c + 0][a_r] = bv.x; Bs[nb][a_c + 1][a_r] = bv.y;
                Bs[nb][a_c + 2][a_r] = bv.z; Bs[nb][a_c + 3][a_r] = bv.w;
            }
        }
        __syncthreads();
        buf ^= 1;
    }

    if constexpr (ARGMAX) {
        __shared__ float sval[128][16];
        __shared__ int   sidx[128][16];
        const int ct = tid & 15;
#pragma unroll
        for (int i = 0; i < 8; i++) {
            float best = acc[i][0];
            int bj = 0;
#pragma unroll
            for (int j = 1; j < 8; j++)
                if (acc[i][j] > best) { best = acc[i][j]; bj = j; }
            sval[tr + i][ct] = best;
            sidx[tr + i][ct] = tc + bj;   // local col within 128-tile
        }
        __syncthreads();
        if (tid < 128) {
            float best = sval[tid][0];
            int bl = sidx[tid][0];
            for (int c = 1; c < 16; c++) {
                float v = sval[tid][c];
                if (v > best) { best = v; bl = sidx[tid][c]; }
            }
            g_pval[(size_t)(row0 + tid) * 8 + blockIdx.x] = best;
            g_pidx[(size_t)(row0 + tid) * 8 + blockIdx.x] = col0 + bl;
        }
    } else {
#pragma unroll
        for (int i = 0; i < 8; i++) {
#pragma unroll
            for (int j = 0; j < 8; j++) {
                float v = acc[i][j];
                if (BIAS) v += bias[col0 + tc + j];
                C[(size_t)(row0 + tr + i) * N + col0 + tc + j] = v;
            }
        }
    }
}

__global__ void __launch_bounds__(256)
k_gemm_proj(const float* __restrict__ X, const float* __restrict__ W,
            const float* __restrict__ b) {
    sgemm_body<ROWS, P_DIM, IN_DIM, false, true, false>(X, W, b, g_zpre);
}
__global__ void __launch_bounds__(256) k_gemm_scores() {
    sgemm_body<ROWS, NPENTA, P_DIM, true, false, true>(g_z, g_cent, nullptr, nullptr);
}
__global__ void __launch_bounds__(256)
k_gemm_qkv(const float* __restrict__ W, const float* __restrict__ b) {
    sgemm_body<ROWS, 3 * P_DIM, P_DIM, false, true, false>(g_z, W, b, g_qkv);
}

// ============================================================================
// LayerNorm + GELU + L2-normalize per row
// ============================================================================
__global__ void k_lgn(const float* __restrict__ gam, const float* __restrict__ bet) {
    __shared__ float red[256];
    int row = blockIdx.x, tid = threadIdx.x;
    const float* src = g_zpre + (size_t)row * P_DIM;
    float x0 = src[tid], x1 = src[tid + 256];
    float mu = block_sum(x0 + x1, red, 256, tid) / 512.0f;
    float d0 = x0 - mu, d1 = x1 - mu;
    float var = block_sum(d0 * d0 + d1 * d1, red, 256, tid) / 512.0f;
    float rs = rsqrtf(var + EPS_);
    float y0 = d0 * rs * gam[tid] + bet[tid];
    float y1 = d1 * rs * gam[tid + 256] + bet[tid + 256];
    float h0 = gelu_exact(y0), h1 = gelu_exact(y1);
    float nrm = sqrtf(block_sum(h0 * h0 + h1 * h1, red, 256, tid));
    float den = fmaxf(nrm, 1e-12f);
    float* dst = g_z + (size_t)row * P_DIM;
    dst[tid] = h0 / den;
    dst[tid + 256] = h1 / den;
}

// ============================================================================
// Combine 8 col-block argmax partials (ascending order, strict > = first idx)
// ============================================================================
__global__ void k_anchor_reduce() {
    int row = blockIdx.x * 256 + threadIdx.x;
    if (row >= ROWS) return;
    float best = g_pval[(size_t)row * 8];
    int bi = g_pidx[(size_t)row * 8];
#pragma unroll
    for (int c = 1; c < 8; c++) {
        float v = g_pval[(size_t)row * 8 + c];
        if (v > best) { best = v; bi = g_pidx[(size_t)row * 8 + c]; }
    }
    g_anchor[row] = bi;
}

// ============================================================================
// Exact 128-NN per (batch, anchor) via histogram select on key
// (dist_bits<<32)|idx — same set as jax top_k(-dist) incl. tie-breaks.
// ============================================================================
__global__ void __launch_bounds__(256) void_guard();  // (unused fwd decl filler)

__global__ void __launch_bounds__(256) k_topk(const float* __restrict__ positions) {
    __shared__ unsigned int db[S_];          // 8 KB   dist bits per token
    __shared__ unsigned int hist[2048];      // 8 KB
    __shared__ unsigned long long cand[S_];  // 16 KB  boundary-bucket candidates
    __shared__ int scan[256];
    __shared__ int sb[4];                    // bstar, c0, nsel, ncand
    int blk = blockIdx.x;
    int b = blk >> 10;
    int a = blk & 1023;
    int tid = threadIdx.x;
    if (tid == 0) { sb[2] = 0; sb[3] = 0; }
    float pq = positions[a];
    for (int i = tid; i < 2048; i += 256) hist[i] = 0;
    __syncthreads();
    for (int i = tid; i < S_; i += 256) {
        float p = positions[g_anchor[b * S_ + i]];
        unsigned int u = __float_as_uint(fabsf(pq - p));
        db[i] = u;
        atomicAdd(&hist[u >> 21], 1u);
    }
    __syncthreads();
    // per-thread sum of 8 buckets + inclusive scan over 256
    int base = tid * 8;
    unsigned int c[8];
    int loc = 0;
#pragma unroll
    for (int j = 0; j < 8; j++) { c[j] = hist[base + j]; loc += (int)c[j]; }
    int v = loc;
    scan[tid] = v;
    __syncthreads();
    for (int off = 1; off < 256; off <<= 1) {
        int t = (tid >= off) ? scan[tid - off] : 0;
        __syncthreads();
        v += t;
        scan[tid] = v;
        __syncthreads();
    }
    int run = v - loc;   // exclusive prefix
#pragma unroll
    for (int j = 0; j < 8; j++) {
        int cnt = (int)c[j];
        if (run < KNEI && run + cnt >= KNEI) { sb[0] = base + j; sb[1] = run; }
        run += cnt;
    }
    __syncthreads();
    unsigned int bstar = (unsigned int)sb[0];
    int c0 = sb[1];
    int out = blk * KNEI;
    for (int i = tid; i < S_; i += 256) {
        unsigned int bkt = db[i] >> 21;
        if (bkt < bstar) {
            int s = atomicAdd(&sb[2], 1);
            g_routes[out + s] = i;
        } else if (bkt == bstar) {
            int cp = atomicAdd(&sb[3], 1);
            cand[cp] = ((unsigned long long)db[i] << 32) | (unsigned int)i;
        }
    }
    __syncthreads();
    int ncand = sb[3];
    int need = KNEI - c0;
    int P = 1;
    while (P < ncand) P <<= 1;
    if (P < 2) P = 2;
    for (int i = ncand + tid; i < P; i += 256) cand[i] = 0xFFFFFFFFFFFFFFFFull;
    __syncthreads();
    for (int len = 2; len <= P; len <<= 1) {
        for (int j = len >> 1; j > 0; j >>= 1) {
            for (int i = tid; i < P; i += 256) {
                int p = i ^ j;
                if (p > i) {
                    bool up = ((i & len) == 0);
                    unsigned long long x = cand[i], y = cand[p];
                    if ((x > y) == up) { cand[i] = y; cand[p] = x; }
                }
            }
            __syncthreads();
        }
    }
    for (int r = tid; r < need; r += 256) g_routes[out + c0 + r] = (int)(cand[r] & 0xffffffffu);
}

// ============================================================================
// Gathered attention: block per (b,q), heads sequential, full 256-thread use.
// ============================================================================
__global__ void __launch_bounds__(256) k_attention() {
    __shared__ int   rbase[KNEI];
    __shared__ float qv[HD_];
    __shared__ float sc[KNEI];
    __shared__ float sc2[2][KNEI];
    __shared__ float opart[4][HD_];
    __shared__ float red2[2];
    __shared__ float tile[KNEI][HD_ + 1];
    int row = blockIdx.x;
    int b = row >> 11;
    int tid = threadIdx.x;
    int anc = g_anchor[row];
    if (tid < KNEI)
        rbase[tid] = (b * S_ + g_routes[((b << 10) + anc) * KNEI + tid]) * (3 * P_DIM);
    __syncthreads();

    const int i_sc = tid & 127, half = tid >> 7, d0 = half * 32;
    const int d_o = tid & 63, q4 = tid >> 6;

    for (int h = 0; h < H_; h++) {
        int hoff = h * HD_;
        if (tid < HD_) qv[tid] = g_qkv[(size_t)row * (3 * P_DIM) + hoff + tid];
        // K tile
#pragma unroll 4
        for (int e = tid; e < KNEI * HD_; e += 256) {
            int i = e >> 6, d = e & 63;
            tile[i][d] = g_qkv[rbase[i] + P_DIM + hoff + d];
        }
        __syncthreads();
        // scores: 2 threads per neighbor
        {
            float s = 0.f;
#pragma unroll
            for (int d = 0; d < 32; d++) s += qv[d0 + d] * tile[i_sc][d0 + d];
            sc2[half][i_sc] = s;
        }
        __syncthreads();
        if (tid < KNEI) sc[tid] = (sc2[0][tid] + sc2[1][tid]) * 0.125f;
        // V tile (overwrite; score reads finished before last sync)
#pragma unroll 4
        for (int e = tid; e < KNEI * HD_; e += 256) {
            int i = e >> 6, d = e & 63;
            tile[i][d] = g_qkv[rbase[i] + 2 * P_DIM + hoff + d];
        }
        __syncthreads();
        if (tid < 32) {
            float m = fmaxf(fmaxf(sc[tid], sc[tid + 32]),
                            fmaxf(sc[tid + 64], sc[tid + 96]));
#pragma unroll
            for (int o = 16; o; o >>= 1) m = fmaxf(m, __shfl_xor_sync(0xffffffffu, m, o));
            red2[0] = m;
        }
        __syncthreads();
        float mx = red2[0];
        if (tid < KNEI) sc[tid] = expf(sc[tid] - mx);
        __syncthreads();
        if (tid < 32) {
            float s = sc[tid] + sc[tid + 32] + sc[tid + 64] + sc[tid + 96];
#pragma unroll
            for (int o = 16; o; o >>= 1) s += __shfl_xor_sync(0xffffffffu, s, o);
            red2[1] = s;
        }
        __syncthreads();
        // output: 4 threads per dim
        {
            float o = 0.f;
            int ib = q4 * 32;
#pragma unroll
            for (int i = 0; i < 32; i++) o += sc[ib + i] * tile[ib + i][d_o];
            opart[q4][d_o] = o;
        }
        __syncthreads();
        if (tid < HD_) {
            float o = (opart[0][tid] + opart[1][tid] + opart[2][tid] + opart[3][tid]) / red2[1];
            g_att[(size_t)row * P_DIM + hoff + tid] = o;
        }
        __syncthreads();
    }
}

// ============================================================================
// Pooling + out projection folded after the mean
// ============================================================================
__global__ void k_attmean1() {
    int bb = blockIdx.x;
    int b  = bb >> 6;
    int dc = (bb >> 4) & 3;
    int sc = bb & 15;
    int d = dc * 128 + threadIdx.x;
    float s = 0.f;
    int base = (b * S_ + sc * 128) * P_DIM + d;
    for (int t = 0; t < 128; t++) s += g_att[base + t * P_DIM];
    g_attpart[(b * 16 + sc) * P_DIM + d] = s;
}
__global__ void k_attmean2() {
    int b = blockIdx.x >> 2, dc = blockIdx.x & 3;
    int d = dc * 128 + threadIdx.x;
    float s = 0.f;
#pragma unroll
    for (int p = 0; p < 16; p++) s += g_attpart[(b * 16 + p) * P_DIM + d];
    g_attmean[b * P_DIM + d] = s * (1.0f / (float)S_);
}
__global__ void k_pool(const float* __restrict__ outW, const float* __restrict__ outb) {
    __shared__ float am[P_DIM];
    int b = blockIdx.x, n = threadIdx.x;
    am[n] = g_attmean[b * P_DIM + n];
    __syncthreads();
    float acc = outb[n];
#pragma unroll 8
    for (int k = 0; k < P_DIM; k++) acc += am[k] * outW[k * P_DIM + n];
    g_pooled[b * P_DIM + n] = acc;
}

// ============================================================================
// Per-scale MLP heads
// ============================================================================
template <int TWOS>
__global__ void k_mlp1(const float* __restrict__ w1, const float* __restrict__ b1,
                       const float* __restrict__ gam, const float* __restrict__ bet) {
    __shared__ float pr[P_DIM];
    __shared__ float red[TWOS];
    int b = blockIdx.x, j = threadIdx.x;
    for (int k = j; k < P_DIM; k += TWOS) pr[k] = g_pooled[b * P_DIM + k];
    __syncthreads();
    float t = b1[j];
#pragma unroll 8
    for (int k = 0; k < P_DIM; k++) t += pr[k] * w1[k * TWOS + j];
    float mu = block_sum(t, red, TWOS, j) / (float)TWOS;
    float d = t - mu;
    float var = block_sum(d * d, red, TWOS, j) / (float)TWOS;
    float y = d * rsqrtf(var + EPS_) * gam[j] + bet[j];
    g_h[b * 1024 + j] = gelu_exact(y);
}

template <int TWOS, int SS, int OFF>
__global__ void k_mlp2(const float* __restrict__ w2, const float* __restrict__ b2,
                       float* __restrict__ out) {
    __shared__ float hr[TWOS];
    int b = blockIdx.x, j = threadIdx.x;
    for (int k = j; k < TWOS; k += SS) hr[k] = g_h[b * 1024 + k];
    __syncthreads();
    float acc = b2[j];
#pragma unroll 8
    for (int k = 0; k < TWOS; k++) acc += hr[k] * w2[k * SS + j];
    out[b * 896 + OFF + j] = acc;
}

// ============================================================================
// Launch
// ============================================================================
extern "C" void kernel_launch(void* const* d_in, const int* in_sizes, int n_in,
                              void* d_out, int out_size) {
    const float* X      = (const float*)d_in[0];
    const float* penta  = (const float*)d_in[1];
    const float* poss   = (const float*)d_in[2];
    const float* projW  = (const float*)d_in[3];
    const float* projb  = (const float*)d_in[4];
    const float* lng    = (const float*)d_in[5];
    const float* lnb    = (const float*)d_in[6];
    const float* qkvW   = (const float*)d_in[7];
    const float* qkvb   = (const float*)d_in[8];
    const float* outW   = (const float*)d_in[9];
    const float* outb   = (const float*)d_in[10];
    const float* w1a = (const float*)d_in[11]; const float* b1a = (const float*)d_in[12];
    const float* ga  = (const float*)d_in[13]; const float* bba = (const float*)d_in[14];
    const float* w2a = (const float*)d_in[15]; const float* b2a = (const float*)d_in[16];
    const float* w1b = (const float*)d_in[17]; const float* b1b = (const float*)d_in[18];
    const float* gb  = (const float*)d_in[19]; const float* bbb = (const float*)d_in[20];
    const float* w2b = (const float*)d_in[21]; const float* b2b = (const float*)d_in[22];
    const float* w1c = (const float*)d_in[23]; const float* b1c = (const float*)d_in[24];
    const float* gc  = (const float*)d_in[25]; const float* bbc = (const float*)d_in[26];
    const float* w2c = (const float*)d_in[27]; const float* b2c = (const float*)d_in[28];
    float* out = (float*)d_out;

    k_cent<<<NPENTA, 256>>>(penta);
    k_gemm_proj<<<dim3(P_DIM / 128, ROWS / 128), 256>>>(X, projW, projb);
    k_lgn<<<ROWS, 256>>>(lng, lnb);
    k_gemm_scores<<<dim3(NPENTA / 128, ROWS / 128), 256>>>();
    k_anchor_reduce<<<ROWS / 256, 256>>>();
    k_gemm_qkv<<<dim3(3 * P_DIM / 128, ROWS / 128), 256>>>(qkvW, qkvb);
    k_topk<<<B_ * NPENTA, 256>>>(poss);
    k_attention<<<ROWS, 256>>>();
    k_attmean1<<<128, 128>>>();
    k_attmean2<<<8, 128>>>();
    k_pool<<<B_, 512>>>(outW, outb);

    k_mlp1<256><<<B_, 256>>>(w1a, b1a, ga, bba);
    k_mlp2<256, 128, 0><<<B_, 128>>>(w2a, b2a, out);
    k_mlp1<512><<<B_, 512>>>(w1b, b1b, gb, bbb);
    k_mlp2<512, 256, 128><<<B_, 256>>>(w2b, b2b, out);
    k_mlp1<1024><<<B_, 1024>>>(w1c, b1c, gc, bbc);
    k_mlp2<1024, 512, 384><<<B_, 512>>>(w2c, b2c, out);
}

// round 5
// speedup vs baseline: 1.9035x; 1.4177x over previous
#include <cuda_runtime.h>
#include <math.h>

// ============================================================================
// Problem constants
// ============================================================================
#define B_     2
#define S_     2048
#define IN_DIM 1024
#define P_DIM  512
#define H_     8
#define HD_    64
#define NPENTA 1024
#define KNEI   128
#define ROWS   (B_ * S_)        // 4096
#define EPS_   1e-5f

// ============================================================================
// Scratch (static device globals — no runtime allocation)
// ============================================================================
__device__ float g_cent[NPENTA * P_DIM];
__device__ float g_zpre[ROWS * P_DIM];
__device__ float g_z[ROWS * P_DIM];
__device__ float g_pval[ROWS * 8];
__device__ int   g_pidx[ROWS * 8];
__device__ int   g_anchor[ROWS];
__device__ int   g_routes[B_ * NPENTA * KNEI];
__device__ float g_qkv[ROWS * 3 * P_DIM];
__device__ float g_att[ROWS * P_DIM];
__device__ float g_attpart[B_ * 16 * P_DIM];
__device__ float g_attmean[B_ * P_DIM];
__device__ float g_pooled[B_ * P_DIM];
__device__ float g_h[B_ * 1024];

// ============================================================================
// Helpers
// ============================================================================
__device__ __forceinline__ float gelu_exact(float x) {
    return 0.5f * x * (1.0f + erff(x * 0.70710678118654752440f));
}

__device__ __forceinline__ float block_sum(float v, float* red, int n, int tid) {
    red[tid] = v;
    __syncthreads();
    for (int s = n >> 1; s > 0; s >>= 1) {
        if (tid < s) red[tid] += red[tid + s];
        __syncthreads();
    }
    float r = red[0];
    __syncthreads();
    return r;
}

__device__ __forceinline__ float warp_sum(float v) {
#pragma unroll
    for (int o = 16; o; o >>= 1) v += __shfl_xor_sync(0xffffffffu, v, o);
    return v;
}

// ============================================================================
// centroids = normalize(mean over 5 vertices)
// ============================================================================
__global__ void k_cent(const float* __restrict__ penta) {
    __shared__ float red[256];
    int p = blockIdx.x, tid = threadIdx.x;
    float v[2];
    float ss = 0.f;
#pragma unroll
    for (int r = 0; r < 2; r++) {
        int d = tid + r * 256;
        float s = 0.f;
#pragma unroll
        for (int i = 0; i < 5; i++) s += penta[(p * 5 + i) * P_DIM + d];
        v[r] = s / 5.0f;
        ss += v[r] * v[r];
    }
    float tot = block_sum(ss, red, 256, tid);
    float den = fmaxf(sqrtf(tot), 1e-12f);
#pragma unroll
    for (int r = 0; r < 2; r++) g_cent[p * P_DIM + tid + r * 256] = v[r] / den;
}

// ============================================================================
// Double-buffered tiled SGEMM: C = A[M,K] @ B (+bias). TB: B is [N,K].
// 256 threads, 128x128 tile, BK=8, 8x8 per thread. Optional fused argmax.
// ============================================================================
template <int M, int N, int K, bool TB, bool BIAS, bool ARGMAX>
__device__ __forceinline__ void sgemm_body(const float* __restrict__ A,
                                           const float* __restrict__ Bm,
                                           const float* __restrict__ bias,
                                           float* __restrict__ C) {
    __shared__ float As[2][8][128];
    __shared__ float Bs[2][8][128];
    const int tid  = threadIdx.x;
    const int row0 = blockIdx.y * 128, col0 = blockIdx.x * 128;
    const int tr = (tid >> 4) << 3;
    const int tc = (tid & 15) << 3;
    const int a_r = tid >> 1, a_c = (tid & 1) << 2;
    const int b_r = tid >> 5, b_c = (tid & 31) << 2;

    const float* aPtr = A + (size_t)(row0 + a_r) * K + a_c;

    float acc[8][8];
#pragma unroll
    for (int i = 0; i < 8; i++)
#pragma unroll
        for (int j = 0; j < 8; j++) acc[i][j] = 0.f;

    float4 av = *(const float4*)(aPtr);
    float4 bv;
    if (!TB) bv = *(const float4*)(Bm + (size_t)b_r * N + col0 + b_c);
    else     bv = *(const float4*)(Bm + (size_t)(col0 + a_r) * K + a_c);
    As[0][a_c + 0][a_r] = av.x; As[0][a_c + 1][a_r] = av.y;
    As[0][a_c + 2][a_r] = av.z; As[0][a_c + 3][a_r] = av.w;
    if (!TB) {
        *(float4*)(&Bs[0][b_r][b_c]) = bv;
    } else {
        Bs[0][a_c + 0][a_r] = bv.x; Bs[0][a_c + 1][a_r] = bv.y;
        Bs[0][a_c + 2][a_r] = bv.z; Bs[0][a_c + 3][a_r] = bv.w;
    }
    __syncthreads();

    int buf = 0;
    for (int k0 = 8; k0 < K + 8; k0 += 8) {
        if (k0 < K) {
            av = *(const float4*)(aPtr + k0);
            if (!TB) bv = *(const float4*)(Bm + (size_t)(k0 + b_r) * N + col0 + b_c);
            else     bv = *(const float4*)(Bm + (size_t)(col0 + a_r) * K + k0 + a_c);
        }
#pragma unroll
        for (int kk = 0; kk < 8; kk++) {
            float ar[8], br[8];
            *(float4*)(ar)     = *(const float4*)&As[buf][kk][tr];
            *(float4*)(ar + 4) = *(const float4*)&As[buf][kk][tr + 4];
            *(float4*)(br)     = *(const float4*)&Bs[buf][kk][tc];
            *(float4*)(br + 4) = *(const float4*)&Bs[buf][kk][tc + 4];
#pragma unroll
            for (int i = 0; i < 8; i++)
#pragma unroll
                for (int j = 0; j < 8; j++) acc[i][j] += ar[i] * br[j];
        }
        if (k0 < K) {
            int nb = buf ^ 1;
            As[nb][a_c + 0][a_r] = av.x; As[nb][a_c + 1][a_r] = av.y;
            As[nb][a_c + 2][a_r] = av.z; As[nb][a_c + 3][a_r] = av.w;
            if (!TB) {
                *(float4*)(&Bs[nb][b_r][b_c]) = bv;
            } else {
                Bs[nb][a_c + 0][a_r] = bv.x; Bs[nb][a_c + 1][a_r] = bv.y;
                Bs[nb][a_c + 2][a_r] = bv.z; Bs[nb][a_c + 3][a_r] = bv.w;
            }
        }
        __syncthreads();
        buf ^= 1;
    }

    if constexpr (ARGMAX) {
        __shared__ float sval[128][16];
        __shared__ int   sidx[128][16];
        const int ct = tid & 15;
#pragma unroll
        for (int i = 0; i < 8; i++) {
            float best = acc[i][0];
            int bj = 0;
#pragma unroll
            for (int j = 1; j < 8; j++)
                if (acc[i][j] > best) { best = acc[i][j]; bj = j; }
            sval[tr + i][ct] = best;
            sidx[tr + i][ct] = tc + bj;
        }
        __syncthreads();
        if (tid < 128) {
            float best = sval[tid][0];
            int bl = sidx[tid][0];
            for (int c = 1; c < 16; c++) {
                float v = sval[tid][c];
                if (v > best) { best = v; bl = sidx[tid][c]; }
            }
            g_pval[(size_t)(row0 + tid) * 8 + blockIdx.x] = best;
            g_pidx[(size_t)(row0 + tid) * 8 + blockIdx.x] = col0 + bl;
        }
    } else {
#pragma unroll
        for (int i = 0; i < 8; i++) {
#pragma unroll
            for (int j = 0; j < 8; j++) {
                float v = acc[i][j];
                if (BIAS) v += bias[col0 + tc + j];
                C[(size_t)(row0 + tr + i) * N + col0 + tc + j] = v;
            }
        }
    }
}

__global__ void __launch_bounds__(256)
k_gemm_proj(const float* __restrict__ X, const float* __restrict__ W,
            const float* __restrict__ b) {
    sgemm_body<ROWS, P_DIM, IN_DIM, false, true, false>(X, W, b, g_zpre);
}
__global__ void __launch_bounds__(256) k_gemm_scores() {
    sgemm_body<ROWS, NPENTA, P_DIM, true, false, true>(g_z, g_cent, nullptr, nullptr);
}
__global__ void __launch_bounds__(256)
k_gemm_qkv(const float* __restrict__ W, const float* __restrict__ b) {
    sgemm_body<ROWS, 3 * P_DIM, P_DIM, false, true, false>(g_z, W, b, g_qkv);
}

// ============================================================================
// LayerNorm + GELU + L2-normalize per row (512). 128 threads, float4/thread,
// shfl-based reductions.
// ============================================================================
__global__ void __launch_bounds__(128)
k_lgn(const float* __restrict__ gam, const float* __restrict__ bet) {
    __shared__ float wred[4];
    int row = blockIdx.x, tid = threadIdx.x;
    int lane = tid & 31, warp = tid >> 5;
    const float4* src = (const float4*)(g_zpre + (size_t)row * P_DIM);
    float4 x = src[tid];
    // mean
    float s = warp_sum(x.x + x.y + x.z + x.w);
    if (lane == 0) wred[warp] = s;
    __syncthreads();
    float mu = (wred[0] + wred[1] + wred[2] + wred[3]) * (1.0f / 512.0f);
    __syncthreads();
    float4 d = make_float4(x.x - mu, x.y - mu, x.z - mu, x.w - mu);
    // var
    s = warp_sum(d.x * d.x + d.y * d.y + d.z * d.z + d.w * d.w);
    if (lane == 0) wred[warp] = s;
    __syncthreads();
    float var = (wred[0] + wred[1] + wred[2] + wred[3]) * (1.0f / 512.0f);
    __syncthreads();
    float rs = rsqrtf(var + EPS_);
    float4 gv = ((const float4*)gam)[tid];
    float4 bv = ((const float4*)bet)[tid];
    float4 hh;
    hh.x = gelu_exact(d.x * rs * gv.x + bv.x);
    hh.y = gelu_exact(d.y * rs * gv.y + bv.y);
    hh.z = gelu_exact(d.z * rs * gv.z + bv.z);
    hh.w = gelu_exact(d.w * rs * gv.w + bv.w);
    // L2 norm
    s = warp_sum(hh.x * hh.x + hh.y * hh.y + hh.z * hh.z + hh.w * hh.w);
    if (lane == 0) wred[warp] = s;
    __syncthreads();
    float nrm = sqrtf(wred[0] + wred[1] + wred[2] + wred[3]);
    float inv = 1.0f / fmaxf(nrm, 1e-12f);
    float4* dst = (float4*)(g_z + (size_t)row * P_DIM);
    dst[tid] = make_float4(hh.x * inv, hh.y * inv, hh.z * inv, hh.w * inv);
}

// ============================================================================
// Combine 8 col-block argmax partials (ascending order, strict > = first idx)
// ============================================================================
__global__ void k_anchor_reduce() {
    int row = blockIdx.x * 256 + threadIdx.x;
    if (row >= ROWS) return;
    float best = g_pval[(size_t)row * 8];
    int bi = g_pidx[(size_t)row * 8];
#pragma unroll
    for (int c = 1; c < 8; c++) {
        float v = g_pval[(size_t)row * 8 + c];
        if (v > best) { best = v; bi = g_pidx[(size_t)row * 8 + c]; }
    }
    g_anchor[row] = bi;
}

// ============================================================================
// Exact 128-NN per (batch, anchor) via histogram select on key
// (dist_bits<<32)|idx — same set as jax top_k(-dist) incl. tie-breaks.
// ============================================================================
__global__ void __launch_bounds__(256) k_topk(const float* __restrict__ positions) {
    __shared__ unsigned int db[S_];
    __shared__ unsigned int hist[2048];
    __shared__ unsigned long long cand[S_];
    __shared__ int scan[256];
    __shared__ int sb[4];
    int blk = blockIdx.x;
    int b = blk >> 10;
    int a = blk & 1023;
    int tid = threadIdx.x;
    if (tid == 0) { sb[2] = 0; sb[3] = 0; }
    float pq = positions[a];
    for (int i = tid; i < 2048; i += 256) hist[i] = 0;
    __syncthreads();
    for (int i = tid; i < S_; i += 256) {
        float p = positions[g_anchor[b * S_ + i]];
        unsigned int u = __float_as_uint(fabsf(pq - p));
        db[i] = u;
        atomicAdd(&hist[u >> 21], 1u);
    }
    __syncthreads();
    int base = tid * 8;
    unsigned int c[8];
    int loc = 0;
#pragma unroll
    for (int j = 0; j < 8; j++) { c[j] = hist[base + j]; loc += (int)c[j]; }
    int v = loc;
    scan[tid] = v;
    __syncthreads();
    for (int off = 1; off < 256; off <<= 1) {
        int t = (tid >= off) ? scan[tid - off] : 0;
        __syncthreads();
        v += t;
        scan[tid] = v;
        __syncthreads();
    }
    int run = v - loc;
#pragma unroll
    for (int j = 0; j < 8; j++) {
        int cnt = (int)c[j];
        if (run < KNEI && run + cnt >= KNEI) { sb[0] = base + j; sb[1] = run; }
        run += cnt;
    }
    __syncthreads();
    unsigned int bstar = (unsigned int)sb[0];
    int c0 = sb[1];
    int out = blk * KNEI;
    for (int i = tid; i < S_; i += 256) {
        unsigned int bkt = db[i] >> 21;
        if (bkt < bstar) {
            int s2 = atomicAdd(&sb[2], 1);
            g_routes[out + s2] = i;
        } else if (bkt == bstar) {
            int cp = atomicAdd(&sb[3], 1);
            cand[cp] = ((unsigned long long)db[i] << 32) | (unsigned int)i;
        }
    }
    __syncthreads();
    int ncand = sb[3];
    int need = KNEI - c0;
    int P = 1;
    while (P < ncand) P <<= 1;
    if (P < 2) P = 2;
    for (int i = ncand + tid; i < P; i += 256) cand[i] = 0xFFFFFFFFFFFFFFFFull;
    __syncthreads();
    for (int len = 2; len <= P; len <<= 1) {
        for (int j = len >> 1; j > 0; j >>= 1) {
            for (int i = tid; i < P; i += 256) {
                int p = i ^ j;
                if (p > i) {
                    bool up = ((i & len) == 0);
                    unsigned long long x = cand[i], y = cand[p];
                    if ((x > y) == up) { cand[i] = y; cand[p] = x; }
                }
            }
            __syncthreads();
        }
    }
    for (int r = tid; r < need; r += 256) g_routes[out + c0 + r] = (int)(cand[r] & 0xffffffffu);
}

// ============================================================================
// Gathered attention: block per (b,q); WARP PER HEAD, barrier-free mainloop.
// Scores: 8 lanes per neighbor (2x float4 K loads + xor-shfl reduce), 4
// neighbors in flight. Softmax in shfl. V: 2 dims/lane, float2 loads.
// ============================================================================
__global__ void __launch_bounds__(256) k_attention() {
    __shared__ int   rbase[KNEI];
    __shared__ float sc[H_][KNEI];
    int row = blockIdx.x;
    int b = row >> 11;
    int tid = threadIdx.x;
    int warp = tid >> 5, lane = tid & 31;
    int anc = g_anchor[row];
    if (tid < KNEI)
        rbase[tid] = (b * S_ + g_routes[((b << 10) + anc) * KNEI + tid]) * (3 * P_DIM);
    __syncthreads();

    const int h = warp;
    const int hoff = h * HD_;
    const size_t qrow = (size_t)row * (3 * P_DIM);
    const int qd = (lane & 7) * 8;        // this lane's 8-dim slice
    const int ng = lane >> 3;             // neighbor subgroup 0..3

    float4 q0 = *(const float4*)&g_qkv[qrow + hoff + qd];
    float4 q1 = *(const float4*)&g_qkv[qrow + hoff + qd + 4];

#pragma unroll 4
    for (int rep = 0; rep < 32; rep++) {
        int n = rep * 4 + ng;
        const float* kr = &g_qkv[(size_t)rbase[n] + P_DIM + hoff + qd];
        float4 k0 = *(const float4*)kr;
        float4 k1 = *(const float4*)(kr + 4);
        float s = q0.x * k0.x + q0.y * k0.y + q0.z * k0.z + q0.w * k0.w
                + q1.x * k1.x + q1.y * k1.y + q1.z * k1.z + q1.w * k1.w;
        s += __shfl_xor_sync(0xffffffffu, s, 4);
        s += __shfl_xor_sync(0xffffffffu, s, 2);
        s += __shfl_xor_sync(0xffffffffu, s, 1);
        if ((lane & 7) == 0) sc[h][n] = s * 0.125f;
    }
    __syncwarp();

    float v0 = sc[h][lane], v1 = sc[h][lane + 32];
    float v2 = sc[h][lane + 64], v3 = sc[h][lane + 96];
    float m = fmaxf(fmaxf(v0, v1), fmaxf(v2, v3));
#pragma unroll
    for (int o = 16; o; o >>= 1) m = fmaxf(m, __shfl_xor_sync(0xffffffffu, m, o));
    v0 = expf(v0 - m); v1 = expf(v1 - m); v2 = expf(v2 - m); v3 = expf(v3 - m);
    float ssum = warp_sum(v0 + v1 + v2 + v3);
    float inv = 1.0f / ssum;
    sc[h][lane] = v0; sc[h][lane + 32] = v1;
    sc[h][lane + 64] = v2; sc[h][lane + 96] = v3;
    __syncwarp();

    float2 acc = make_float2(0.f, 0.f);
    const int d2 = lane * 2;
#pragma unroll 4
    for (int i = 0; i < KNEI; i++) {
        float p = sc[h][i];
        float2 vv = *(const float2*)&g_qkv[(size_t)rbase[i] + 2 * P_DIM + hoff + d2];
        acc.x += p * vv.x;
        acc.y += p * vv.y;
    }
    float* dst = &g_att[(size_t)row * P_DIM + hoff + d2];
    dst[0] = acc.x * inv;
    dst[1] = acc.y * inv;
}

// ============================================================================
// Pooling + out projection folded after the mean
// ============================================================================
__global__ void k_attmean1() {
    int bb = blockIdx.x;
    int b  = bb >> 6;
    int dc = (bb >> 4) & 3;
    int sc = bb & 15;
    int d = dc * 128 + threadIdx.x;
    float s = 0.f;
    int base = (b * S_ + sc * 128) * P_DIM + d;
    for (int t = 0; t < 128; t++) s += g_att[base + t * P_DIM];
    g_attpart[(b * 16 + sc) * P_DIM + d] = s;
}
__global__ void k_attmean2() {
    int b = blockIdx.x >> 2, dc = blockIdx.x & 3;
    int d = dc * 128 + threadIdx.x;
    float s = 0.f;
#pragma unroll
    for (int p = 0; p < 16; p++) s += g_attpart[(b * 16 + p) * P_DIM + d];
    g_attmean[b * P_DIM + d] = s * (1.0f / (float)S_);
}
__global__ void k_pool(const float* __restrict__ outW, const float* __restrict__ outb) {
    __shared__ float am[P_DIM];
    int b = blockIdx.x, n = threadIdx.x;
    am[n] = g_attmean[b * P_DIM + n];
    __syncthreads();
    float acc = outb[n];
#pragma unroll 8
    for (int k = 0; k < P_DIM; k++) acc += am[k] * outW[k * P_DIM + n];
    g_pooled[b * P_DIM + n] = acc;
}

// ============================================================================
// Per-scale MLP heads
// ============================================================================
template <int TWOS>
__global__ void k_mlp1(const float* __restrict__ w1, const float* __restrict__ b1,
                       const float* __restrict__ gam, const float* __restrict__ bet) {
    __shared__ float pr[P_DIM];
    __shared__ float red[TWOS];
    int b = blockIdx.x, j = threadIdx.x;
    for (int k = j; k < P_DIM; k += TWOS) pr[k] = g_pooled[b * P_DIM + k];
    __syncthreads();
    float t = b1[j];
#pragma unroll 8
    for (int k = 0; k < P_DIM; k++) t += pr[k] * w1[k * TWOS + j];
    float mu = block_sum(t, red, TWOS, j) / (float)TWOS;
    float d = t - mu;
    float var = block_sum(d * d, red, TWOS, j) / (float)TWOS;
    float y = d * rsqrtf(var + EPS_) * gam[j] + bet[j];
    g_h[b * 1024 + j] = gelu_exact(y);
}

template <int TWOS, int SS, int OFF>
__global__ void k_mlp2(const float* __restrict__ w2, const float* __restrict__ b2,
                       float* __restrict__ out) {
    __shared__ float hr[TWOS];
    int b = blockIdx.x, j = threadIdx.x;
    for (int k = j; k < TWOS; k += SS) hr[k] = g_h[b * 1024 + k];
    __syncthreads();
    float acc = b2[j];
#pragma unroll 8
    for (int k = 0; k < TWOS; k++) acc += hr[k] * w2[k * SS + j];
    out[b * 896 + OFF + j] = acc;
}

// ============================================================================
// Launch
// ============================================================================
extern "C" void kernel_launch(void* const* d_in, const int* in_sizes, int n_in,
                              void* d_out, int out_size) {
    const float* X      = (const float*)d_in[0];
    const float* penta  = (const float*)d_in[1];
    const float* poss   = (const float*)d_in[2];
    const float* projW  = (const float*)d_in[3];
    const float* projb  = (const float*)d_in[4];
    const float* lng    = (const float*)d_in[5];
    const float* lnb    = (const float*)d_in[6];
    const float* qkvW   = (const float*)d_in[7];
    const float* qkvb   = (const float*)d_in[8];
    const float* outW   = (const float*)d_in[9];
    const float* outb   = (const float*)d_in[10];
    const float* w1a = (const float*)d_in[11]; const float* b1a = (const float*)d_in[12];
    const float* ga  = (const float*)d_in[13]; const float* bba = (const float*)d_in[14];
    const float* w2a = (const float*)d_in[15]; const float* b2a = (const float*)d_in[16];
    const float* w1b = (const float*)d_in[17]; const float* b1b = (const float*)d_in[18];
    const float* gb  = (const float*)d_in[19]; const float* bbb = (const float*)d_in[20];
    const float* w2b = (const float*)d_in[21]; const float* b2b = (const float*)d_in[22];
    const float* w1c = (const float*)d_in[23]; const float* b1c = (const float*)d_in[24];
    const float* gc  = (const float*)d_in[25]; const float* bbc = (const float*)d_in[26];
    const float* w2c = (const float*)d_in[27]; const float* b2c = (const float*)d_in[28];
    float* out = (float*)d_out;

    k_cent<<<NPENTA, 256>>>(penta);
    k_gemm_proj<<<dim3(P_DIM / 128, ROWS / 128), 256>>>(X, projW, projb);
    k_lgn<<<ROWS, 128>>>(lng, lnb);
    k_gemm_scores<<<dim3(NPENTA / 128, ROWS / 128), 256>>>();
    k_anchor_reduce<<<ROWS / 256, 256>>>();
    k_gemm_qkv<<<dim3(3 * P_DIM / 128, ROWS / 128), 256>>>(qkvW, qkvb);
    k_topk<<<B_ * NPENTA, 256>>>(poss);
    k_attention<<<ROWS, 256>>>();
    k_attmean1<<<128, 128>>>();
    k_attmean2<<<8, 128>>>();
    k_pool<<<B_, 512>>>(outW, outb);

    k_mlp1<256><<<B_, 256>>>(w1a, b1a, ga, bba);
    k_mlp2<256, 128, 0><<<B_, 128>>>(w2a, b2a, out);
    k_mlp1<512><<<B_, 512>>>(w1b, b1b, gb, bbb);
    k_mlp2<512, 256, 128><<<B_, 256>>>(w2b, b2b, out);
    k_mlp1<1024><<<B_, 1024>>>(w1c, b1c, gc, bbc);
    k_mlp2<1024, 512, 384><<<B_, 512>>>(w2c, b2c, out);
}